// round 8
// baseline (speedup 1.0000x reference)
#include <cuda_runtime.h>
#include <math.h>
#include <cstdint>

#define NUM_E   8
#define BATCH   4
#define CCAP    1024
#define DMODEL  1024
#define DFF     4096

// CTA tile 128x256, BK=32; 16 warps in 2x8 grid, each warp 64x32. 512 threads.
#define BM 128
#define BN 256
#define BK 32
#define NTHREADS 512

// Row-major smem tiles, 32 words (128B) per row, XOR-swizzled 16B chunks:
//   chunk' = chunk ^ (row & 7)
#define A_TILE_BYTES (BM * BK * 4)                    // 16384
#define B_TILE_BYTES (BN * BK * 4)                    // 32768
#define STAGE_BYTES  (A_TILE_BYTES + B_TILE_BYTES)    // 49152
#define SMEM_BYTES   (2 * STAGE_BYTES + 128)

// 512 MB fp32 scratch for h = gelu(x@W1^T + b1)
__device__ float g_h[134217728];

__device__ __forceinline__ uint32_t smem_u32(const void* p) {
    uint32_t a;
    asm("{ .reg .u64 t; cvta.to.shared.u64 t, %1; cvt.u32.u64 %0, t; }" : "=r"(a) : "l"(p));
    return a;
}
__device__ __forceinline__ unsigned f2tf32(float x) {
    unsigned y;
    asm("cvt.rna.tf32.f32 %0, %1;" : "=r"(y) : "f"(x));
    return y;
}
__device__ __forceinline__ void sts128(uint32_t addr, uint4 v) {
    asm volatile("st.shared.v4.b32 [%0], {%1,%2,%3,%4};"
                 :: "r"(addr), "r"(v.x), "r"(v.y), "r"(v.z), "r"(v.w) : "memory");
}
__device__ __forceinline__ unsigned lds32(uint32_t addr) {
    unsigned v;
    asm volatile("ld.shared.b32 %0, [%1];" : "=r"(v) : "r"(addr));
    return v;
}
__device__ __forceinline__ void mma_tf32(float acc[4], const unsigned a[4], const unsigned b[2]) {
    asm volatile(
        "mma.sync.aligned.m16n8k8.row.col.f32.tf32.tf32.f32 "
        "{%0,%1,%2,%3}, {%4,%5,%6,%7}, {%8,%9}, {%0,%1,%2,%3};\n"
        : "+f"(acc[0]), "+f"(acc[1]), "+f"(acc[2]), "+f"(acc[3])
        : "r"(a[0]), "r"(a[1]), "r"(a[2]), "r"(a[3]),
          "r"(b[0]), "r"(b[1]));
}
__device__ __forceinline__ float gelu_exact(float x) {
    return 0.5f * x * (1.0f + erff(x * 0.7071067811865476f));
}

// Grouped NT GEMM: O[grp][m][n] = sum_k A[grp][m][k] * W[e][n][k] + bias[e][n] (opt gelu)
template<int NTOT, int KTOT, bool GELU>
__global__ void __launch_bounds__(NTHREADS, 1)
grouped_ffn(const float* __restrict__ A0, const float* __restrict__ W0,
            const float* __restrict__ bias0, float* __restrict__ O0)
{
    extern __shared__ char smraw[];
    const uint32_t sm32 = (smem_u32(smraw) + 127u) & ~127u;

    const int tid  = threadIdx.x;
    const int wid  = tid >> 5;
    const int lane = tid & 31;
    const int wr   = wid >> 3;    // 0..1  (64-row slab)
    const int wc   = wid & 7;     // 0..7  (32-col slab)
    const int g    = lane >> 2;   // 0..7
    const int tq   = lane & 3;    // 0..3

    const int grp = blockIdx.z;
    const int e   = grp & (NUM_E - 1);
    const int bm  = blockIdx.y * BM;
    const int bn  = blockIdx.x * BN;

    const float* A = A0 + (size_t)grp * CCAP * KTOT + (size_t)bm * KTOT;
    const float* W = W0 + (size_t)e * NTOT * KTOT + (size_t)bn * KTOT;

    // ---- writer plan: thread t -> row (t>>3)+64i, 16B chunk (t&7) ----
    const int wrow = tid >> 3;    // 0..63
    const int wchk = tid & 7;     // 0..7
    const float* Ag = A + (size_t)wrow * KTOT + wchk * 4;
    const float* Wg = W + (size_t)wrow * KTOT + wchk * 4;

    // swizzled STS byte offsets within a tile (row&7 invariant under +64)
    uint32_t aso[2], bso[4];
    {
        const uint32_t sc = (uint32_t)(wchk ^ (wrow & 7)) << 4;
        #pragma unroll
        for (int i = 0; i < 2; ++i) aso[i] = (uint32_t)(wrow + 64 * i) * 128 + sc;
        #pragma unroll
        for (int i = 0; i < 4; ++i) bso[i] = (uint32_t)(wrow + 64 * i) * 128 + sc;
    }

    float4 ra[2], rb[4];
    auto LDG_TILE = [&](int kt) {
        const size_t k0 = (size_t)kt * BK;
        #pragma unroll
        for (int i = 0; i < 2; ++i)
            ra[i] = *reinterpret_cast<const float4*>(Ag + (size_t)(i * 64) * KTOT + k0);
        #pragma unroll
        for (int i = 0; i < 4; ++i)
            rb[i] = *reinterpret_cast<const float4*>(Wg + (size_t)(i * 64) * KTOT + k0);
    };
    auto STS_TILE = [&](int d) {
        const uint32_t abase = sm32 + d * STAGE_BYTES;
        #pragma unroll
        for (int i = 0; i < 2; ++i)
            sts128(abase + aso[i],
                   make_uint4(f2tf32(ra[i].x), f2tf32(ra[i].y), f2tf32(ra[i].z), f2tf32(ra[i].w)));
        const uint32_t bbase = abase + A_TILE_BYTES;
        #pragma unroll
        for (int i = 0; i < 4; ++i)
            sts128(bbase + bso[i],
                   make_uint4(f2tf32(rb[i].x), f2tf32(rb[i].y), f2tf32(rb[i].z), f2tf32(rb[i].w)));
    };

    // ---- scalar-LDS fragment plan ----
    // element (r,k): byte = r*128 + ((k>>2)^(r&7))*16 + (k&3)*4; r&7 == g for all reads.
    const uint32_t aRow0 = (uint32_t)(wr * 64 + g) * 128 + tq * 4;   // + mi*2048 (+1024 for r+8)
    const uint32_t bRow0 = (uint32_t)(wc * 32 + g) * 128 + tq * 4;   // + ni*1024
    const uint32_t gx    = (uint32_t)g << 4;

    float acc[4][4][4];
    #pragma unroll
    for (int mi = 0; mi < 4; ++mi)
        #pragma unroll
        for (int ni = 0; ni < 4; ++ni)
            #pragma unroll
            for (int c = 0; c < 4; ++c)
                acc[mi][ni][c] = 0.0f;

    auto COMPUTE = [&](uint32_t sbase) {
        #pragma unroll
        for (int kb = 0; kb < 4; ++kb) {
            const uint32_t c0 = ((uint32_t)(kb * 32)) ^ gx;   // ((2kb)^g)<<4
            unsigned af[4][4], bf[4][2];
            #pragma unroll
            for (int mi = 0; mi < 4; ++mi) {
                const uint32_t base = sbase + aRow0 + mi * 2048;
                af[mi][0] = lds32(base + c0);
                af[mi][1] = lds32(base + 1024 + c0);
                af[mi][2] = lds32(base + (c0 ^ 16));
                af[mi][3] = lds32(base + 1024 + (c0 ^ 16));
            }
            #pragma unroll
            for (int ni = 0; ni < 4; ++ni) {
                const uint32_t base = sbase + A_TILE_BYTES + bRow0 + ni * 1024;
                bf[ni][0] = lds32(base + c0);
                bf[ni][1] = lds32(base + (c0 ^ 16));
            }
            #pragma unroll
            for (int mi = 0; mi < 4; ++mi)
                #pragma unroll
                for (int ni = 0; ni < 4; ++ni)
                    mma_tf32(acc[mi][ni], af[mi], bf[ni]);
        }
    };

    const int NK = KTOT / BK;

    LDG_TILE(0);
    STS_TILE(0);
    __syncthreads();

    #pragma unroll 1
    for (int kt = 0; kt < NK; ++kt) {
        const int s = kt & 1;
        const bool more = (kt + 1 < NK);
        if (more) LDG_TILE(kt + 1);            // latency covered by full compute below
        COMPUTE(sm32 + s * STAGE_BYTES);
        if (more) STS_TILE(s ^ 1);             // s^1 free: all warps passed prior sync
        __syncthreads();
    }

    // Epilogue: +bias, optional exact gelu, fp32 stores
    const float* bias = bias0 + (size_t)e * NTOT + bn;
    float* O = O0 + (size_t)grp * CCAP * NTOT + bn;

    #pragma unroll
    for (int mi = 0; mi < 4; ++mi) {
        const int r0 = bm + wr * 64 + mi * 16 + g;
        #pragma unroll
        for (int ni = 0; ni < 4; ++ni) {
            const int cc = wc * 32 + ni * 8 + tq * 2;
            const float2 bv = *reinterpret_cast<const float2*>(bias + cc);
            float v00 = acc[mi][ni][0] + bv.x;
            float v01 = acc[mi][ni][1] + bv.y;
            float v10 = acc[mi][ni][2] + bv.x;
            float v11 = acc[mi][ni][3] + bv.y;
            if (GELU) {
                v00 = gelu_exact(v00); v01 = gelu_exact(v01);
                v10 = gelu_exact(v10); v11 = gelu_exact(v11);
            }
            *reinterpret_cast<float2*>(O + (size_t)r0 * NTOT + cc)       = make_float2(v00, v01);
            *reinterpret_cast<float2*>(O + (size_t)(r0 + 8) * NTOT + cc) = make_float2(v10, v11);
        }
    }
}

extern "C" void kernel_launch(void* const* d_in, const int* in_sizes, int n_in,
                              void* d_out, int out_size)
{
    const float* inputs = (const float*)d_in[0];  // [4, 8192, 1024]
    const float* w1     = (const float*)d_in[1];  // [8, 4096, 1024]
    const float* b1     = (const float*)d_in[2];  // [8, 4096]
    const float* w2     = (const float*)d_in[3];  // [8, 1024, 4096]
    const float* b2     = (const float*)d_in[4];  // [8, 1024]
    float*       out    = (float*)d_out;          // [4, 8192, 1024]

    void* hptr = nullptr;
    cudaGetSymbolAddress(&hptr, g_h);
    float* h = (float*)hptr;

    cudaFuncSetAttribute(grouped_ffn<DFF, DMODEL, true>,
                         cudaFuncAttributeMaxDynamicSharedMemorySize, SMEM_BYTES);
    cudaFuncSetAttribute(grouped_ffn<DMODEL, DFF, false>,
                         cudaFuncAttributeMaxDynamicSharedMemorySize, SMEM_BYTES);

    // GEMM1 + gelu: h[grp][c][f]  (32 groups, M=1024, N=4096, K=1024)
    {
        dim3 grid(DFF / BN, CCAP / BM, BATCH * NUM_E);
        grouped_ffn<DFF, DMODEL, true><<<grid, NTHREADS, SMEM_BYTES>>>(inputs, w1, b1, h);
    }
    // GEMM2: out[grp][c][d]  (32 groups, M=1024, N=1024, K=4096)
    {
        dim3 grid(DMODEL / BN, CCAP / BM, BATCH * NUM_E);
        grouped_ffn<DMODEL, DFF, false><<<grid, NTHREADS, SMEM_BYTES>>>(h, w2, b2, out);
    }
}

// round 9
// speedup vs baseline: 1.0964x; 1.0964x over previous
#include <cuda_runtime.h>
#include <math.h>
#include <cstdint>

#define NUM_E   8
#define BATCH   4
#define CCAP    1024
#define DMODEL  1024
#define DFF     4096

// CTA tile 128x256, BK=32; 8 warps in 2x4 grid, each warp 64x64. 256 threads.
#define BM 128
#define BN 256
#define BK 32
#define NSTAGE 3

// Row-major smem tiles, 32 words (128B) per row, XOR-swizzled 16B chunks:
//   chunk' = chunk ^ (row & 7)
#define A_TILE_BYTES (BM * BK * 4)                    // 16384
#define B_TILE_BYTES (BN * BK * 4)                    // 32768
#define STAGE_BYTES  (A_TILE_BYTES + B_TILE_BYTES)    // 49152
#define SMEM_BYTES   (NSTAGE * STAGE_BYTES + 128)     // 147584

// 512 MB fp32 scratch for h = gelu(x@W1^T + b1)
__device__ float g_h[134217728];

__device__ __forceinline__ uint32_t smem_u32(const void* p) {
    uint32_t a;
    asm("{ .reg .u64 t; cvta.to.shared.u64 t, %1; cvt.u32.u64 %0, t; }" : "=r"(a) : "l"(p));
    return a;
}
__device__ __forceinline__ unsigned f2tf32(float x) {
    unsigned y;
    asm("cvt.rna.tf32.f32 %0, %1;" : "=r"(y) : "f"(x));
    return y;
}
__device__ __forceinline__ float ldsf(uint32_t addr) {
    float v;
    asm volatile("ld.shared.f32 %0, [%1];" : "=f"(v) : "r"(addr));
    return v;
}
__device__ __forceinline__ void cp16(uint32_t dst, const void* src) {
    asm volatile("cp.async.cg.shared.global [%0], [%1], 16;"
                 :: "r"(dst), "l"(src) : "memory");
}
__device__ __forceinline__ void mma_tf32(float acc[4], const unsigned a[4], const unsigned b[2]) {
    asm volatile(
        "mma.sync.aligned.m16n8k8.row.col.f32.tf32.tf32.f32 "
        "{%0,%1,%2,%3}, {%4,%5,%6,%7}, {%8,%9}, {%0,%1,%2,%3};\n"
        : "+f"(acc[0]), "+f"(acc[1]), "+f"(acc[2]), "+f"(acc[3])
        : "r"(a[0]), "r"(a[1]), "r"(a[2]), "r"(a[3]),
          "r"(b[0]), "r"(b[1]));
}
__device__ __forceinline__ float gelu_exact(float x) {
    return 0.5f * x * (1.0f + erff(x * 0.7071067811865476f));
}

// Grouped NT GEMM: O[grp][m][n] = sum_k A[grp][m][k] * W[e][n][k] + bias[e][n] (opt gelu)
template<int NTOT, int KTOT, bool GELU>
__global__ void __launch_bounds__(256, 1)
grouped_ffn(const float* __restrict__ A0, const float* __restrict__ W0,
            const float* __restrict__ bias0, float* __restrict__ O0)
{
    extern __shared__ char smraw[];
    const uint32_t sm32 = (smem_u32(smraw) + 127u) & ~127u;

    const int tid  = threadIdx.x;
    const int wid  = tid >> 5;
    const int lane = tid & 31;
    const int wr   = wid >> 2;    // 0..1  (64-row slab)
    const int wc   = wid & 3;     // 0..3  (64-col slab)
    const int g    = lane >> 2;   // 0..7
    const int tq   = lane & 3;    // 0..3

    const int grp = blockIdx.z;
    const int e   = grp & (NUM_E - 1);
    const int bm  = blockIdx.y * BM;
    const int bn  = blockIdx.x * BN;

    const float* A = A0 + (size_t)grp * CCAP * KTOT + (size_t)bm * KTOT;
    const float* W = W0 + (size_t)e * NTOT * KTOT + (size_t)bn * KTOT;

    // ---- async-copy plan: thread t -> row (t>>3)+32i, 16B chunk (t&7) ----
    const int wrow = tid >> 3;    // 0..31
    const int wchk = tid & 7;     // 0..7
    const float* Ag = A + (size_t)wrow * KTOT + wchk * 4;
    const float* Wg = W + (size_t)wrow * KTOT + wchk * 4;

    uint32_t aso[4], bso[8];      // swizzled dst byte offsets (row&7 invariant under +32)
    {
        const uint32_t sc = (uint32_t)(wchk ^ (wrow & 7)) << 4;
        #pragma unroll
        for (int i = 0; i < 4; ++i) aso[i] = (uint32_t)(wrow + 32 * i) * 128 + sc;
        #pragma unroll
        for (int i = 0; i < 8; ++i) bso[i] = (uint32_t)(wrow + 32 * i) * 128 + sc;
    }

    auto CP_TILE = [&](int kt, int s) {
        const size_t k0 = (size_t)kt * BK;
        const uint32_t abase = sm32 + s * STAGE_BYTES;
        #pragma unroll
        for (int i = 0; i < 4; ++i)
            cp16(abase + aso[i], Ag + (size_t)(i * 32) * KTOT + k0);
        const uint32_t bbase = abase + A_TILE_BYTES;
        #pragma unroll
        for (int i = 0; i < 8; ++i)
            cp16(bbase + bso[i], Wg + (size_t)(i * 32) * KTOT + k0);
        asm volatile("cp.async.commit_group;" ::: "memory");
    };

    // ---- scalar-LDS fragment plan (reader does tf32 rounding) ----
    // element (r,k): byte = r*128 + ((k>>2)^(r&7))*16 + (k&3)*4; r&7 == g for all reads.
    const uint32_t aRow0 = (uint32_t)(wr * 64 + g) * 128 + tq * 4;   // + mi*2048 (+1024 for r+8)
    const uint32_t bRow0 = (uint32_t)(wc * 64 + g) * 128 + tq * 4;   // + ni*1024
    const uint32_t gx    = (uint32_t)g << 4;

    float acc[4][8][4];
    #pragma unroll
    for (int mi = 0; mi < 4; ++mi)
        #pragma unroll
        for (int ni = 0; ni < 8; ++ni)
            #pragma unroll
            for (int c = 0; c < 4; ++c)
                acc[mi][ni][c] = 0.0f;

    auto COMPUTE = [&](uint32_t sbase) {
        #pragma unroll
        for (int kb = 0; kb < 4; ++kb) {
            const uint32_t c0 = ((uint32_t)(kb * 32)) ^ gx;   // ((2kb)^g)<<4
            unsigned af[4][4], bf[8][2];
            #pragma unroll
            for (int mi = 0; mi < 4; ++mi) {
                const uint32_t base = sbase + aRow0 + mi * 2048;
                af[mi][0] = f2tf32(ldsf(base + c0));
                af[mi][1] = f2tf32(ldsf(base + 1024 + c0));
                af[mi][2] = f2tf32(ldsf(base + (c0 ^ 16)));
                af[mi][3] = f2tf32(ldsf(base + 1024 + (c0 ^ 16)));
            }
            #pragma unroll
            for (int ni = 0; ni < 8; ++ni) {
                const uint32_t base = sbase + A_TILE_BYTES + bRow0 + ni * 1024;
                bf[ni][0] = f2tf32(ldsf(base + c0));
                bf[ni][1] = f2tf32(ldsf(base + (c0 ^ 16)));
            }
            #pragma unroll
            for (int mi = 0; mi < 4; ++mi)
                #pragma unroll
                for (int ni = 0; ni < 8; ++ni)
                    mma_tf32(acc[mi][ni], af[mi], bf[ni]);
        }
    };

    const int NK = KTOT / BK;

    // Prologue: stages 0 and 1 in flight (groups G0, G1)
    CP_TILE(0, 0);
    CP_TILE(1, 1);

    int s_cur = 0;                 // kt % 3
    int s_nxt = 2;                 // (kt+2) % 3

    #pragma unroll 1
    for (int kt = 0; kt < NK; ++kt) {
        // At this point groups G0..G_{kt+1} are committed; need G_kt complete.
        if (kt + 1 < NK) asm volatile("cp.async.wait_group 1;" ::: "memory");
        else             asm volatile("cp.async.wait_group 0;" ::: "memory");
        __syncthreads();           // all warps done reading stage (kt-1)%3 == s_nxt

        if (kt + 2 < NK) CP_TILE(kt + 2, s_nxt);   // commits G_{kt+2}

        COMPUTE(sm32 + s_cur * STAGE_BYTES);

        s_cur = (s_cur + 1 == NSTAGE) ? 0 : s_cur + 1;
        s_nxt = (s_nxt + 1 == NSTAGE) ? 0 : s_nxt + 1;
    }

    // Epilogue: +bias, optional exact gelu, fp32 stores
    const float* bias = bias0 + (size_t)e * NTOT + bn;
    float* O = O0 + (size_t)grp * CCAP * NTOT + bn;

    #pragma unroll
    for (int mi = 0; mi < 4; ++mi) {
        const int r0 = bm + wr * 64 + mi * 16 + g;
        #pragma unroll
        for (int ni = 0; ni < 8; ++ni) {
            const int cc = wc * 64 + ni * 8 + tq * 2;
            const float2 bv = *reinterpret_cast<const float2*>(bias + cc);
            float v00 = acc[mi][ni][0] + bv.x;
            float v01 = acc[mi][ni][1] + bv.y;
            float v10 = acc[mi][ni][2] + bv.x;
            float v11 = acc[mi][ni][3] + bv.y;
            if (GELU) {
                v00 = gelu_exact(v00); v01 = gelu_exact(v01);
                v10 = gelu_exact(v10); v11 = gelu_exact(v11);
            }
            *reinterpret_cast<float2*>(O + (size_t)r0 * NTOT + cc)       = make_float2(v00, v01);
            *reinterpret_cast<float2*>(O + (size_t)(r0 + 8) * NTOT + cc) = make_float2(v10, v11);
        }
    }
}

extern "C" void kernel_launch(void* const* d_in, const int* in_sizes, int n_in,
                              void* d_out, int out_size)
{
    const float* inputs = (const float*)d_in[0];  // [4, 8192, 1024]
    const float* w1     = (const float*)d_in[1];  // [8, 4096, 1024]
    const float* b1     = (const float*)d_in[2];  // [8, 4096]
    const float* w2     = (const float*)d_in[3];  // [8, 1024, 4096]
    const float* b2     = (const float*)d_in[4];  // [8, 1024]
    float*       out    = (float*)d_out;          // [4, 8192, 1024]

    void* hptr = nullptr;
    cudaGetSymbolAddress(&hptr, g_h);
    float* h = (float*)hptr;

    cudaFuncSetAttribute(grouped_ffn<DFF, DMODEL, true>,
                         cudaFuncAttributeMaxDynamicSharedMemorySize, SMEM_BYTES);
    cudaFuncSetAttribute(grouped_ffn<DMODEL, DFF, false>,
                         cudaFuncAttributeMaxDynamicSharedMemorySize, SMEM_BYTES);

    // GEMM1 + gelu: h[grp][c][f]  (32 groups, M=1024, N=4096, K=1024)
    {
        dim3 grid(DFF / BN, CCAP / BM, BATCH * NUM_E);
        grouped_ffn<DFF, DMODEL, true><<<grid, 256, SMEM_BYTES>>>(inputs, w1, b1, h);
    }
    // GEMM2: out[grp][c][d]  (32 groups, M=1024, N=1024, K=4096)
    {
        dim3 grid(DMODEL / BN, CCAP / BM, BATCH * NUM_E);
        grouped_ffn<DMODEL, DFF, false><<<grid, 256, SMEM_BYTES>>>(h, w2, b2, out);
    }
}

// round 12
// speedup vs baseline: 1.1000x; 1.0033x over previous
#include <cuda_runtime.h>
#include <math.h>
#include <cstdint>

#define NUM_E   8
#define BATCH   4
#define CCAP    1024
#define DMODEL  1024
#define DFF     4096

// CTA tile 128x256, BK=32; 8 warps in 2x4 grid, each warp 64x64. 256 threads.
#define BM 128
#define BN 256
#define BK 32
#define NSTAGE 3

// Row-major smem tiles, 32 words (128B) per row, XOR-swizzled 16B chunks:
//   chunk' = chunk ^ (row & 7)
#define A_TILE_BYTES (BM * BK * 4)                    // 16384
#define B_TILE_BYTES (BN * BK * 4)                    // 32768
#define STAGE_BYTES  (A_TILE_BYTES + B_TILE_BYTES)    // 49152
#define SMEM_BYTES   (NSTAGE * STAGE_BYTES + 128)     // 147584

// 512 MB fp32 scratch for h = gelu(x@W1^T + b1)
__device__ float g_h[134217728];

__device__ __forceinline__ uint32_t smem_u32(const void* p) {
    uint32_t a;
    asm("{ .reg .u64 t; cvta.to.shared.u64 t, %1; cvt.u32.u64 %0, t; }" : "=r"(a) : "l"(p));
    return a;
}
// pure (non-volatile): compiler may schedule freely
__device__ __forceinline__ unsigned f2tf32(float x) {
    unsigned y;
    asm("cvt.rna.tf32.f32 %0, %1;" : "=r"(y) : "f"(x));
    return y;
}
__device__ __forceinline__ void cp16(uint32_t dst, const void* src) {
    asm volatile("cp.async.cg.shared.global [%0], [%1], 16;"
                 :: "r"(dst), "l"(src) : "memory");
}
__device__ __forceinline__ void mma_tf32(float acc[4], const unsigned a[4], const unsigned b[2]) {
    asm volatile(
        "mma.sync.aligned.m16n8k8.row.col.f32.tf32.tf32.f32 "
        "{%0,%1,%2,%3}, {%4,%5,%6,%7}, {%8,%9}, {%0,%1,%2,%3};\n"
        : "+f"(acc[0]), "+f"(acc[1]), "+f"(acc[2]), "+f"(acc[3])
        : "r"(a[0]), "r"(a[1]), "r"(a[2]), "r"(a[3]),
          "r"(b[0]), "r"(b[1]));
}
__device__ __forceinline__ float gelu_exact(float x) {
    return 0.5f * x * (1.0f + erff(x * 0.7071067811865476f));
}

// Grouped NT GEMM: O[grp][m][n] = sum_k A[grp][m][k] * W[e][n][k] + bias[e][n] (opt gelu)
template<int NTOT, int KTOT, bool GELU>
__global__ void __launch_bounds__(256, 1)
grouped_ffn(const float* __restrict__ A0, const float* __restrict__ W0,
            const float* __restrict__ bias0, float* __restrict__ O0)
{
    extern __shared__ char smraw[];
    const uint32_t sm32  = (smem_u32(smraw) + 127u) & ~127u;
    const char*    smp   = smraw + (sm32 - smem_u32(smraw));   // same aligned base, pointer form

    const int tid  = threadIdx.x;
    const int wid  = tid >> 5;
    const int lane = tid & 31;
    const int wr   = wid >> 2;    // 0..1  (64-row slab)
    const int wc   = wid & 3;     // 0..3  (64-col slab)
    const int g    = lane >> 2;   // 0..7
    const int tq   = lane & 3;    // 0..3

    const int grp = blockIdx.z;
    const int e   = grp & (NUM_E - 1);
    const int bm  = blockIdx.y * BM;
    const int bn  = blockIdx.x * BN;

    const float* A = A0 + (size_t)grp * CCAP * KTOT + (size_t)bm * KTOT;
    const float* W = W0 + (size_t)e * NTOT * KTOT + (size_t)bn * KTOT;

    // ---- async-copy plan: thread t -> row (t>>3)+32i, 16B chunk (t&7) ----
    const int wrow = tid >> 3;    // 0..31
    const int wchk = tid & 7;     // 0..7
    const float* Ag = A + (size_t)wrow * KTOT + wchk * 4;
    const float* Wg = W + (size_t)wrow * KTOT + wchk * 4;

    uint32_t aso[4], bso[8];      // swizzled dst byte offsets (row&7 invariant under +32)
    {
        const uint32_t sc = (uint32_t)(wchk ^ (wrow & 7)) << 4;
        #pragma unroll
        for (int i = 0; i < 4; ++i) aso[i] = (uint32_t)(wrow + 32 * i) * 128 + sc;
        #pragma unroll
        for (int i = 0; i < 8; ++i) bso[i] = (uint32_t)(wrow + 32 * i) * 128 + sc;
    }

    auto CP_TILE = [&](int kt, int s) {
        const size_t k0 = (size_t)kt * BK;
        const uint32_t abase = sm32 + s * STAGE_BYTES;
        #pragma unroll
        for (int i = 0; i < 4; ++i)
            cp16(abase + aso[i], Ag + (size_t)(i * 32) * KTOT + k0);
        const uint32_t bbase = abase + A_TILE_BYTES;
        #pragma unroll
        for (int i = 0; i < 8; ++i)
            cp16(bbase + bso[i], Wg + (size_t)(i * 32) * KTOT + k0);
        asm volatile("cp.async.commit_group;" ::: "memory");
    };

    // ---- fragment plan (C++ smem reads; reader does tf32 rounding) ----
    // element (r,k): byte = r*128 + ((k>>2)^(r&7))*16 + (k&3)*4; r&7 == g for all reads.
    const uint32_t aRow0 = (uint32_t)(wr * 64 + g) * 128 + tq * 4;   // + mi*2048 (+1024 for r+8)
    const uint32_t bRow0 = (uint32_t)(wc * 64 + g) * 128 + tq * 4;   // + ni*1024
    const uint32_t gx    = (uint32_t)g << 4;

    float acc[4][8][4];
    #pragma unroll
    for (int mi = 0; mi < 4; ++mi)
        #pragma unroll
        for (int ni = 0; ni < 8; ++ni)
            #pragma unroll
            for (int c = 0; c < 4; ++c)
                acc[mi][ni][c] = 0.0f;

    unsigned fa[2][16], fb[2][16];

    auto LOAD_FRAGS = [&](const char* sbase, int kb, unsigned* pa, unsigned* pb) {
        const uint32_t c0 = ((uint32_t)(kb * 32)) ^ gx;   // ((2kb)^g)<<4
        #pragma unroll
        for (int mi = 0; mi < 4; ++mi) {
            const char* base = sbase + aRow0 + mi * 2048;
            pa[mi * 4 + 0] = f2tf32(*reinterpret_cast<const float*>(base + c0));
            pa[mi * 4 + 1] = f2tf32(*reinterpret_cast<const float*>(base + 1024 + c0));
            pa[mi * 4 + 2] = f2tf32(*reinterpret_cast<const float*>(base + (c0 ^ 16)));
            pa[mi * 4 + 3] = f2tf32(*reinterpret_cast<const float*>(base + 1024 + (c0 ^ 16)));
        }
        #pragma unroll
        for (int ni = 0; ni < 8; ++ni) {
            const char* base = sbase + A_TILE_BYTES + bRow0 + ni * 1024;
            pb[ni * 2 + 0] = f2tf32(*reinterpret_cast<const float*>(base + c0));
            pb[ni * 2 + 1] = f2tf32(*reinterpret_cast<const float*>(base + (c0 ^ 16)));
        }
    };

    auto MMA_FRAGS = [&](const unsigned* pa, const unsigned* pb) {
        #pragma unroll
        for (int mi = 0; mi < 4; ++mi)
            #pragma unroll
            for (int ni = 0; ni < 8; ++ni)
                mma_tf32(acc[mi][ni], pa + mi * 4, pb + ni * 2);
    };

    const int NK = KTOT / BK;

    // Prologue: stages 0 and 1 in flight (groups G0, G1)
    CP_TILE(0, 0);
    CP_TILE(1, 1);

    int s_cur = 0;                 // kt % 3
    int s_nxt = 2;                 // (kt+2) % 3

    #pragma unroll 1
    for (int kt = 0; kt < NK; ++kt) {
        // Groups G0..G_{kt+1} committed; need G_kt complete.
        if (kt + 1 < NK) asm volatile("cp.async.wait_group 1;" ::: "memory");
        else             asm volatile("cp.async.wait_group 0;" ::: "memory");
        __syncthreads();           // all warps done reading stage (kt-1)%3 == s_nxt

        if (kt + 2 < NK) CP_TILE(kt + 2, s_nxt);   // commits G_{kt+2}

        const char* sbase = smp + s_cur * STAGE_BYTES;
        // Software-pipelined fragments: load kb+1 while issuing kb's MMAs.
        LOAD_FRAGS(sbase, 0, fa[0], fb[0]);
        #pragma unroll
        for (int kb = 0; kb < 4; ++kb) {
            if (kb < 3) LOAD_FRAGS(sbase, kb + 1, fa[(kb + 1) & 1], fb[(kb + 1) & 1]);
            MMA_FRAGS(fa[kb & 1], fb[kb & 1]);
        }

        s_cur = (s_cur + 1 == NSTAGE) ? 0 : s_cur + 1;
        s_nxt = (s_nxt + 1 == NSTAGE) ? 0 : s_nxt + 1;
    }

    // Epilogue: +bias, optional exact gelu, fp32 stores
    const float* bias = bias0 + (size_t)e * NTOT + bn;
    float* O = O0 + (size_t)grp * CCAP * NTOT + bn;

    #pragma unroll
    for (int mi = 0; mi < 4; ++mi) {
        const int r0 = bm + wr * 64 + mi * 16 + g;
        #pragma unroll
        for (int ni = 0; ni < 8; ++ni) {
            const int cc = wc * 64 + ni * 8 + tq * 2;
            const float2 bv = *reinterpret_cast<const float2*>(bias + cc);
            float v00 = acc[mi][ni][0] + bv.x;
            float v01 = acc[mi][ni][1] + bv.y;
            float v10 = acc[mi][ni][2] + bv.x;
            float v11 = acc[mi][ni][3] + bv.y;
            if (GELU) {
                v00 = gelu_exact(v00); v01 = gelu_exact(v01);
                v10 = gelu_exact(v10); v11 = gelu_exact(v11);
            }
            *reinterpret_cast<float2*>(O + (size_t)r0 * NTOT + cc)       = make_float2(v00, v01);
            *reinterpret_cast<float2*>(O + (size_t)(r0 + 8) * NTOT + cc) = make_float2(v10, v11);
        }
    }
}

extern "C" void kernel_launch(void* const* d_in, const int* in_sizes, int n_in,
                              void* d_out, int out_size)
{
    const float* inputs = (const float*)d_in[0];  // [4, 8192, 1024]
    const float* w1     = (const float*)d_in[1];  // [8, 4096, 1024]
    const float* b1     = (const float*)d_in[2];  // [8, 4096]
    const float* w2     = (const float*)d_in[3];  // [8, 1024, 4096]
    const float* b2     = (const float*)d_in[4];  // [8, 1024]
    float*       out    = (float*)d_out;          // [4, 8192, 1024]

    void* hptr = nullptr;
    cudaGetSymbolAddress(&hptr, g_h);
    float* h = (float*)hptr;

    cudaFuncSetAttribute(grouped_ffn<DFF, DMODEL, true>,
                         cudaFuncAttributeMaxDynamicSharedMemorySize, SMEM_BYTES);
    cudaFuncSetAttribute(grouped_ffn<DMODEL, DFF, false>,
                         cudaFuncAttributeMaxDynamicSharedMemorySize, SMEM_BYTES);

    // GEMM1 + gelu: h[grp][c][f]  (32 groups, M=1024, N=4096, K=1024)
    {
        dim3 grid(DFF / BN, CCAP / BM, BATCH * NUM_E);
        grouped_ffn<DFF, DMODEL, true><<<grid, 256, SMEM_BYTES>>>(inputs, w1, b1, h);
    }
    // GEMM2: out[grp][c][d]  (32 groups, M=1024, N=1024, K=4096)
    {
        dim3 grid(DMODEL / BN, CCAP / BM, BATCH * NUM_E);
        grouped_ffn<DMODEL, DFF, false><<<grid, 256, SMEM_BYTES>>>(h, w2, b2, out);
    }
}

// round 13
// speedup vs baseline: 1.5791x; 1.4355x over previous
#include <cuda_runtime.h>
#include <cuda_fp16.h>
#include <math.h>
#include <cstdint>

#define NUM_E   8
#define BATCH   4
#define CCAP    1024
#define DMODEL  1024
#define DFF     4096

// CTA tile 128x256, BK=32; 8 warps in 2x4 grid, each warp 64x64. 256 threads.
#define BM 128
#define BN 256
#define BK 32
#define NSTAGE 3

// fp16 smem tiles: 32 halfs (64B data) per row, padded to 80B for
// conflict-free fragment reads (bank = (r*20 + tq + c) mod 32, all distinct).
#define ROW_B       80
#define A_TILE_BYTES (BM * ROW_B)                     // 10240
#define B_TILE_BYTES (BN * ROW_B)                     // 20480
#define STAGE_BYTES  (A_TILE_BYTES + B_TILE_BYTES)    // 30720
#define SMEM_BYTES   (NSTAGE * STAGE_BYTES + 128)     // 92288

// 512 MB scratch: fp16 planes.
//   in_h  @ 0          (33,554,432 halfs)
//   w1_h  @ 67108864   (33,554,432 halfs)
//   w2_h  @ 134217728  (33,554,432 halfs)
//   h_h   @ 201326592  (134,217,728 halfs)   [gelu output of GEMM1]
__device__ __align__(256) unsigned char g_scr[469762048];

#define OFF_IN  0
#define OFF_W1  67108864
#define OFF_W2  134217728
#define OFF_H   201326592

__device__ __forceinline__ uint32_t smem_u32(const void* p) {
    uint32_t a;
    asm("{ .reg .u64 t; cvta.to.shared.u64 t, %1; cvt.u32.u64 %0, t; }" : "=r"(a) : "l"(p));
    return a;
}
__device__ __forceinline__ void cp16(uint32_t dst, const void* src) {
    asm volatile("cp.async.cg.shared.global [%0], [%1], 16;"
                 :: "r"(dst), "l"(src) : "memory");
}
__device__ __forceinline__ void mma_f16(float acc[4], const unsigned a[4], const unsigned b[2]) {
    asm volatile(
        "mma.sync.aligned.m16n8k16.row.col.f32.f16.f16.f32 "
        "{%0,%1,%2,%3}, {%4,%5,%6,%7}, {%8,%9}, {%0,%1,%2,%3};\n"
        : "+f"(acc[0]), "+f"(acc[1]), "+f"(acc[2]), "+f"(acc[3])
        : "r"(a[0]), "r"(a[1]), "r"(a[2]), "r"(a[3]),
          "r"(b[0]), "r"(b[1]));
}
__device__ __forceinline__ float gelu_exact(float x) {
    return 0.5f * x * (1.0f + erff(x * 0.7071067811865476f));
}

// ---------------- pre-pass: fp32 -> fp16 plane ----------------
__global__ void __launch_bounds__(256, 8)
to_half_kernel(const float* __restrict__ src, __half* __restrict__ dst, int n4)
{
    int i = blockIdx.x * blockDim.x + threadIdx.x;
    int stride = gridDim.x * blockDim.x;
    for (; i < n4; i += stride) {
        float4 v = reinterpret_cast<const float4*>(src)[i];
        __half2 lo = __floats2half2_rn(v.x, v.y);
        __half2 hi = __floats2half2_rn(v.z, v.w);
        uint2 o;
        o.x = *reinterpret_cast<uint32_t*>(&lo);
        o.y = *reinterpret_cast<uint32_t*>(&hi);
        reinterpret_cast<uint2*>(dst)[i] = o;
    }
}

// ---------------- grouped NT GEMM, fp16 operands ----------------
// O[grp][m][n] = sum_k A[grp][m][k] * W[e][n][k] (+bias[e][n], opt gelu)
// GELU=true: writes gelu result as fp16 into Oh (h plane). Else fp32 into Of.
template<int NTOT, int KTOT, bool GELU>
__global__ void __launch_bounds__(256, 1)
grouped_ffn(const __half* __restrict__ A0, const __half* __restrict__ W0,
            const float* __restrict__ bias0,
            float* __restrict__ Of, __half* __restrict__ Oh)
{
    extern __shared__ char smraw[];
    const uint32_t sm32 = (smem_u32(smraw) + 127u) & ~127u;
    const char*    smp  = smraw + (sm32 - smem_u32(smraw));

    const int tid  = threadIdx.x;
    const int wid  = tid >> 5;
    const int lane = tid & 31;
    const int wr   = wid >> 2;    // 0..1  (64-row slab)
    const int wc   = wid & 3;     // 0..3  (64-col slab)
    const int g    = lane >> 2;   // 0..7
    const int tq   = lane & 3;    // 0..3

    const int grp = blockIdx.z;
    const int e   = grp & (NUM_E - 1);
    const int bm  = blockIdx.y * BM;
    const int bn  = blockIdx.x * BN;

    const __half* A = A0 + (size_t)grp * CCAP * KTOT + (size_t)bm * KTOT;
    const __half* W = W0 + (size_t)e * NTOT * KTOT + (size_t)bn * KTOT;

    // ---- async-copy plan: chunk id -> row id>>2, 16B chunk id&3 (8 halfs) ----
    auto CP_TILE = [&](int kt, int s) {
        const size_t k0 = (size_t)kt * BK;
        const uint32_t abase = sm32 + s * STAGE_BYTES;
        #pragma unroll
        for (int i = 0; i < 2; ++i) {                 // A: 512 chunks / 256 thr
            const int id  = tid + i * 256;
            const int r   = id >> 2, c = id & 3;
            cp16(abase + (uint32_t)r * ROW_B + c * 16,
                 A + (size_t)r * KTOT + k0 + c * 8);
        }
        const uint32_t bbase = abase + A_TILE_BYTES;
        #pragma unroll
        for (int i = 0; i < 4; ++i) {                 // B: 1024 chunks / 256 thr
            const int id  = tid + i * 256;
            const int r   = id >> 2, c = id & 3;
            cp16(bbase + (uint32_t)r * ROW_B + c * 16,
                 W + (size_t)r * KTOT + k0 + c * 8);
        }
        asm volatile("cp.async.commit_group;" ::: "memory");
    };

    // ---- fragment plan (m16n8k16): element (r, k) at byte r*80 + k*2 ----
    // a0 = {A[g][2tq],A[g][2tq+1]} -> b32 @ r*80 + 4tq; a1: +8 rows; a2: +16B; a3: both.
    // b0 = {W[n][2tq],W[n][2tq+1]} @ n*80 + 4tq; b1: +16B.
    const uint32_t aRow0 = (uint32_t)(wr * 64 + g) * ROW_B + tq * 4;  // + mi*16*80
    const uint32_t bRow0 = (uint32_t)(wc * 64 + g) * ROW_B + tq * 4;  // + ni*8*80

    float acc[4][8][4];
    #pragma unroll
    for (int mi = 0; mi < 4; ++mi)
        #pragma unroll
        for (int ni = 0; ni < 8; ++ni)
            #pragma unroll
            for (int c = 0; c < 4; ++c)
                acc[mi][ni][c] = 0.0f;

    auto COMPUTE = [&](const char* sbase) {
        #pragma unroll
        for (int kc = 0; kc < 2; ++kc) {              // two K=16 chunks
            const uint32_t ko = kc * 32;              // +32B per chunk
            unsigned af[4][4], bf[8][2];
            #pragma unroll
            for (int mi = 0; mi < 4; ++mi) {
                const char* base = sbase + aRow0 + mi * (16 * ROW_B) + ko;
                af[mi][0] = *reinterpret_cast<const unsigned*>(base);
                af[mi][1] = *reinterpret_cast<const unsigned*>(base + 8 * ROW_B);
                af[mi][2] = *reinterpret_cast<const unsigned*>(base + 16);
                af[mi][3] = *reinterpret_cast<const unsigned*>(base + 8 * ROW_B + 16);
            }
            #pragma unroll
            for (int ni = 0; ni < 8; ++ni) {
                const char* base = sbase + A_TILE_BYTES + bRow0 + ni * (8 * ROW_B) + ko;
                bf[ni][0] = *reinterpret_cast<const unsigned*>(base);
                bf[ni][1] = *reinterpret_cast<const unsigned*>(base + 16);
            }
            #pragma unroll
            for (int mi = 0; mi < 4; ++mi)
                #pragma unroll
                for (int ni = 0; ni < 8; ++ni)
                    mma_f16(acc[mi][ni], af[mi], bf[ni]);
        }
    };

    const int NK = KTOT / BK;

    CP_TILE(0, 0);
    CP_TILE(1, 1);

    int s_cur = 0, s_nxt = 2;

    #pragma unroll 1
    for (int kt = 0; kt < NK; ++kt) {
        if (kt + 1 < NK) asm volatile("cp.async.wait_group 1;" ::: "memory");
        else             asm volatile("cp.async.wait_group 0;" ::: "memory");
        __syncthreads();

        if (kt + 2 < NK) CP_TILE(kt + 2, s_nxt);

        COMPUTE(smp + s_cur * STAGE_BYTES);

        s_cur = (s_cur + 1 == NSTAGE) ? 0 : s_cur + 1;
        s_nxt = (s_nxt + 1 == NSTAGE) ? 0 : s_nxt + 1;
    }

    // Epilogue
    const float* bias = bias0 + (size_t)e * NTOT + bn;

    #pragma unroll
    for (int mi = 0; mi < 4; ++mi) {
        const int r0 = bm + wr * 64 + mi * 16 + g;
        #pragma unroll
        for (int ni = 0; ni < 8; ++ni) {
            const int cc = wc * 64 + ni * 8 + tq * 2;
            const float2 bv = *reinterpret_cast<const float2*>(bias + cc);
            float v00 = acc[mi][ni][0] + bv.x;
            float v01 = acc[mi][ni][1] + bv.y;
            float v10 = acc[mi][ni][2] + bv.x;
            float v11 = acc[mi][ni][3] + bv.y;
            if (GELU) {
                // gelu in fp32, then store fp16 into h plane
                v00 = gelu_exact(v00); v01 = gelu_exact(v01);
                v10 = gelu_exact(v10); v11 = gelu_exact(v11);
                __half* H = Oh + (size_t)grp * CCAP * NTOT + bn;
                __half2 p0 = __floats2half2_rn(v00, v01);
                __half2 p1 = __floats2half2_rn(v10, v11);
                *reinterpret_cast<__half2*>(H + (size_t)r0 * NTOT + cc)       = p0;
                *reinterpret_cast<__half2*>(H + (size_t)(r0 + 8) * NTOT + cc) = p1;
            } else {
                float* O = Of + (size_t)grp * CCAP * NTOT + bn;
                *reinterpret_cast<float2*>(O + (size_t)r0 * NTOT + cc)       = make_float2(v00, v01);
                *reinterpret_cast<float2*>(O + (size_t)(r0 + 8) * NTOT + cc) = make_float2(v10, v11);
            }
        }
    }
}

extern "C" void kernel_launch(void* const* d_in, const int* in_sizes, int n_in,
                              void* d_out, int out_size)
{
    const float* inputs = (const float*)d_in[0];  // [4, 8192, 1024]
    const float* w1     = (const float*)d_in[1];  // [8, 4096, 1024]
    const float* b1     = (const float*)d_in[2];  // [8, 4096]
    const float* w2     = (const float*)d_in[3];  // [8, 1024, 4096]
    const float* b2     = (const float*)d_in[4];  // [8, 1024]
    float*       out    = (float*)d_out;          // [4, 8192, 1024]

    void* sp = nullptr;
    cudaGetSymbolAddress(&sp, g_scr);
    __half* in_h = (__half*)((char*)sp + OFF_IN);
    __half* w1_h = (__half*)((char*)sp + OFF_W1);
    __half* w2_h = (__half*)((char*)sp + OFF_W2);
    __half* h_h  = (__half*)((char*)sp + OFF_H);

    // Pre-pass: fp32 -> fp16 planes (each 33,554,432 elems = 8,388,608 float4)
    const int N4 = 8388608;
    to_half_kernel<<<2048, 256>>>(inputs, in_h, N4);
    to_half_kernel<<<2048, 256>>>(w1,     w1_h, N4);
    to_half_kernel<<<2048, 256>>>(w2,     w2_h, N4);

    cudaFuncSetAttribute(grouped_ffn<DFF, DMODEL, true>,
                         cudaFuncAttributeMaxDynamicSharedMemorySize, SMEM_BYTES);
    cudaFuncSetAttribute(grouped_ffn<DMODEL, DFF, false>,
                         cudaFuncAttributeMaxDynamicSharedMemorySize, SMEM_BYTES);

    // GEMM1 + gelu: h[grp][c][f]  (32 groups, M=1024, N=4096, K=1024), fp16 out
    {
        dim3 grid(DFF / BN, CCAP / BM, BATCH * NUM_E);
        grouped_ffn<DFF, DMODEL, true><<<grid, 256, SMEM_BYTES>>>(
            in_h, w1_h, b1, nullptr, h_h);
    }
    // GEMM2: out[grp][c][d]  (32 groups, M=1024, N=1024, K=4096), fp32 out
    {
        dim3 grid(DMODEL / BN, CCAP / BM, BATCH * NUM_E);
        grouped_ffn<DMODEL, DFF, false><<<grid, 256, SMEM_BYTES>>>(
            h_h, w2_h, b2, out, nullptr);
    }
}